// round 3
// baseline (speedup 1.0000x reference)
#include <cuda_runtime.h>
#include <math.h>

#define HIDDEN 1024
#define SEQ    2048
#define BATCH  2
#define HEADS  16
#define HD     64
#define MROWS  (BATCH * SEQ)   /* 4096 */

// Scratch (device globals — no allocation allowed). Referenced directly from
// device code; no cudaGetSymbolAddress needed on the host side.
__device__ float g_qkv[(size_t)MROWS * 3 * HIDDEN];  // [4096, 3072]  (h*192 + {q:0,k:64,v:128} + d)
__device__ float g_ctx[(size_t)MROWS * HIDDEN];      // [4096, 1024]  (h*64 + d)

// ---------------------------------------------------------------------------
// SGEMM + bias: C[M,N] = A[M,K] @ B[K,N] + bias[N]
// 128x128 block tile, BK=8, 256 threads, 8x8 per-thread microtile.
// MODE: 0 -> A = d_in x (passed ptr), C = g_qkv
//       1 -> A = g_ctx,              C = d_out (passed ptr)
// ---------------------------------------------------------------------------
template <int MODE>
__global__ void __launch_bounds__(256) sgemm_bias_kernel(
    const float* __restrict__ Aext, const float* __restrict__ B,
    const float* __restrict__ bias, float* __restrict__ Cext,
    int M, int N, int K)
{
    constexpr int BM = 128, BN = 128, BK = 8;
    __shared__ float As[BK][BM];
    __shared__ float Bs[BK][BN];

    const float* A = (MODE == 0) ? Aext : (const float*)g_ctx;
    float*       C = (MODE == 0) ? (float*)g_qkv : Cext;

    const int tid = threadIdx.x;
    const int tr  = tid >> 4;      // 0..15
    const int tc  = tid & 15;      // 0..15
    const int rowBase = blockIdx.y * BM;
    const int colBase = blockIdx.x * BN;

    float acc[8][8];
#pragma unroll
    for (int i = 0; i < 8; i++)
#pragma unroll
        for (int j = 0; j < 8; j++) acc[i][j] = 0.0f;

    const int arow = tid >> 1, acol = (tid & 1) * 4;   // A tile: 128 rows x 8 k
    const int brow = tid >> 5, bcol = (tid & 31) * 4;  // B tile: 8 k x 128 cols

    const float* Aptr = A + (size_t)(rowBase + arow) * K + acol;
    const float* Bptr = B + (size_t)brow * N + colBase + bcol;

    for (int k0 = 0; k0 < K; k0 += BK) {
        float4 av = *(const float4*)(Aptr + k0);
        As[acol + 0][arow] = av.x;
        As[acol + 1][arow] = av.y;
        As[acol + 2][arow] = av.z;
        As[acol + 3][arow] = av.w;
        float4 bv = *(const float4*)(Bptr + (size_t)k0 * N);
        *(float4*)&Bs[brow][bcol] = bv;
        __syncthreads();

#pragma unroll
        for (int kk = 0; kk < BK; kk++) {
            float af[8], bf[8];
            *(float4*)&af[0] = *(const float4*)&As[kk][tr * 8];
            *(float4*)&af[4] = *(const float4*)&As[kk][tr * 8 + 4];
            *(float4*)&bf[0] = *(const float4*)&Bs[kk][tc * 8];
            *(float4*)&bf[4] = *(const float4*)&Bs[kk][tc * 8 + 4];
#pragma unroll
            for (int i = 0; i < 8; i++)
#pragma unroll
                for (int j = 0; j < 8; j++)
                    acc[i][j] += af[i] * bf[j];
        }
        __syncthreads();
    }

#pragma unroll
    for (int i = 0; i < 8; i++) {
        const size_t r = (size_t)(rowBase + tr * 8 + i);
#pragma unroll
        for (int j = 0; j < 8; j++) {
            const int col = colBase + tc * 8 + j;
            C[r * N + col] = acc[i][j] + bias[col];
        }
    }
}

// ---------------------------------------------------------------------------
// Flash attention (RoPE skipped: the reference indexes the rope tables with
// the HEAD index, so within a head the rotation is a constant orthogonal map
// applied to both q and k -> q'.k' = q.k exactly; v is unrotated).
// Br=Bc=64, 256 threads (16x16), each thread owns S rows 4*ty+a, cols tx+16*b.
// Online softmax with per-row (m,l) carried in registers; 16-lane shfl reduce.
// P tile reuses the K smem buffer. ctx written in [b,s,h,d] layout.
// ---------------------------------------------------------------------------
__global__ void __launch_bounds__(256) attn_kernel()
{
    extern __shared__ float sm[];
    float* Qs = sm;                 // 64 x 64            (stride 64)
    float* Ks = sm + 64 * 64;       // 64 x 64, stride 65 (also holds P)
    float* Vs = Ks + 64 * 65;       // 64 x 64            (stride 64)

    const float* qkv = (const float*)g_qkv;
    float* ctx = (float*)g_ctx;

    const int bh = blockIdx.x;           // b*16 + h
    const int b  = bh >> 4;
    const int h  = bh & 15;
    const int q0 = blockIdx.y * 64;
    const int tid = threadIdx.x;
    const int ty = tid >> 4;             // 0..15
    const int tx = tid & 15;             // 0..15

    const float* qbase = qkv + (size_t)b * SEQ * 3072 + h * 192;
    const float* kbase = qbase + 64;
    const float* vbase = qbase + 128;

    // Load Q tile (rows q0..q0+63, 64 dims). 1024 float4 / 256 threads.
#pragma unroll
    for (int r = 0; r < 4; r++) {
        int i4 = tid + r * 256;
        int row = i4 >> 4;
        int d0  = (i4 & 15) * 4;
        float4 v = *(const float4*)&qbase[(size_t)(q0 + row) * 3072 + d0];
        *(float4*)&Qs[row * 64 + d0] = v;
    }

    float m[4], l[4], o[4][4];
#pragma unroll
    for (int a = 0; a < 4; a++) {
        m[a] = -INFINITY;
        l[a] = 0.0f;
#pragma unroll
        for (int c = 0; c < 4; c++) o[a][c] = 0.0f;
    }

    for (int k0 = 0; k0 < SEQ; k0 += 64) {
        __syncthreads();  // Q store on iter 0; protects Ks(P)/Vs reads afterwards
        // Load K (stride 65) and V (stride 64) tiles
#pragma unroll
        for (int r = 0; r < 4; r++) {
            int i4 = tid + r * 256;
            int row = i4 >> 4;
            int d0  = (i4 & 15) * 4;
            float4 kv = *(const float4*)&kbase[(size_t)(k0 + row) * 3072 + d0];
            Ks[row * 65 + d0 + 0] = kv.x;
            Ks[row * 65 + d0 + 1] = kv.y;
            Ks[row * 65 + d0 + 2] = kv.z;
            Ks[row * 65 + d0 + 3] = kv.w;
            float4 vv = *(const float4*)&vbase[(size_t)(k0 + row) * 3072 + d0];
            *(float4*)&Vs[row * 64 + d0] = vv;
        }
        __syncthreads();

        // S = Q K^T  (thread: rows 4*ty+a, cols tx+16*bb)
        float s[4][4];
#pragma unroll
        for (int a = 0; a < 4; a++)
#pragma unroll
            for (int bb = 0; bb < 4; bb++) s[a][bb] = 0.0f;

#pragma unroll 8
        for (int d = 0; d < 64; d++) {
            float qf[4], kf[4];
#pragma unroll
            for (int a = 0; a < 4; a++)  qf[a]  = Qs[(4 * ty + a) * 64 + d];
#pragma unroll
            for (int bb = 0; bb < 4; bb++) kf[bb] = Ks[(tx + 16 * bb) * 65 + d];
#pragma unroll
            for (int a = 0; a < 4; a++)
#pragma unroll
                for (int bb = 0; bb < 4; bb++)
                    s[a][bb] += qf[a] * kf[bb];
        }

        // online softmax (scale 1/8)
#pragma unroll
        for (int a = 0; a < 4; a++) {
#pragma unroll
            for (int bb = 0; bb < 4; bb++) s[a][bb] *= 0.125f;
            float mt = fmaxf(fmaxf(s[a][0], s[a][1]), fmaxf(s[a][2], s[a][3]));
#pragma unroll
            for (int off = 8; off >= 1; off >>= 1)
                mt = fmaxf(mt, __shfl_xor_sync(0xffffffffu, mt, off, 16));
            float mnew  = fmaxf(m[a], mt);
            float alpha = __expf(m[a] - mnew);
            float ls = 0.0f;
#pragma unroll
            for (int bb = 0; bb < 4; bb++) {
                float p = __expf(s[a][bb] - mnew);
                s[a][bb] = p;
                ls += p;
            }
#pragma unroll
            for (int off = 8; off >= 1; off >>= 1)
                ls += __shfl_xor_sync(0xffffffffu, ls, off, 16);
            l[a] = l[a] * alpha + ls;
            m[a] = mnew;
#pragma unroll
            for (int c = 0; c < 4; c++) o[a][c] *= alpha;
        }

        __syncthreads();  // all K reads done before P overwrites the buffer
#pragma unroll
        for (int a = 0; a < 4; a++)
#pragma unroll
            for (int bb = 0; bb < 4; bb++)
                Ks[(4 * ty + a) * 65 + tx + 16 * bb] = s[a][bb];
        __syncthreads();

        // O += P V  (thread: rows 4*ty+a, out dims tx+16*c)
#pragma unroll 8
        for (int j = 0; j < 64; j++) {
            float pf[4], vf[4];
#pragma unroll
            for (int a = 0; a < 4; a++) pf[a] = Ks[(4 * ty + a) * 65 + j];
#pragma unroll
            for (int c = 0; c < 4; c++) vf[c] = Vs[j * 64 + tx + 16 * c];
#pragma unroll
            for (int a = 0; a < 4; a++)
#pragma unroll
                for (int c = 0; c < 4; c++)
                    o[a][c] += pf[a] * vf[c];
        }
    }

    // epilogue: normalize and write ctx[b, s, h*64+d]
    float* cbase = ctx + ((size_t)b * SEQ + q0) * HIDDEN + h * HD;
#pragma unroll
    for (int a = 0; a < 4; a++) {
        float inv = 1.0f / l[a];
#pragma unroll
        for (int c = 0; c < 4; c++)
            cbase[(size_t)(4 * ty + a) * HIDDEN + tx + 16 * c] = o[a][c] * inv;
    }
}

// ---------------------------------------------------------------------------
extern "C" void kernel_launch(void* const* d_in, const int* in_sizes, int n_in,
                              void* d_out, int out_size)
{
    (void)in_sizes; (void)n_in; (void)out_size;
    const float* x     = (const float*)d_in[0];
    const float* qkv_w = (const float*)d_in[1];
    const float* qkv_b = (const float*)d_in[2];
    const float* out_w = (const float*)d_in[3];
    const float* out_b = (const float*)d_in[4];
    float* out = (float*)d_out;

    const int attn_smem = (64 * 64 + 64 * 65 + 64 * 64) * (int)sizeof(float); // 49408
    cudaFuncSetAttribute(attn_kernel, cudaFuncAttributeMaxDynamicSharedMemorySize,
                         attn_smem);

    // 1) QKV projection: g_qkv = x @ qkv_w + qkv_b
    {
        dim3 grid(3 * HIDDEN / 128, MROWS / 128);
        sgemm_bias_kernel<0><<<grid, 256>>>(x, qkv_w, qkv_b, nullptr,
                                            MROWS, 3 * HIDDEN, HIDDEN);
    }
    // 2) Attention (flash, RoPE elided — see analysis)
    {
        dim3 grid(BATCH * HEADS, SEQ / 64);
        attn_kernel<<<grid, 256, attn_smem>>>();
    }
    // 3) Output projection: out = g_ctx @ out_w + out_b
    {
        dim3 grid(HIDDEN / 128, MROWS / 128);
        sgemm_bias_kernel<1><<<grid, 256>>>(nullptr, out_w, out_b, out,
                                            MROWS, HIDDEN, HIDDEN);
    }
}

// round 8
// speedup vs baseline: 1.9827x; 1.9827x over previous
#include <cuda_runtime.h>
#include <cuda_bf16.h>
#include <math.h>
#include <stdint.h>

#define HIDDEN 1024
#define SEQ    2048
#define BATCH  2
#define HEADS  16
#define HD     64
#define MROWS  (BATCH * SEQ)   /* 4096 */

// ---------------------------------------------------------------------------
// Scratch (device globals — no allocation allowed)
// ---------------------------------------------------------------------------
__device__ __align__(16) __nv_bfloat16 g_xhi[(size_t)MROWS * HIDDEN];
__device__ __align__(16) __nv_bfloat16 g_xlo[(size_t)MROWS * HIDDEN];
__device__ __align__(16) __nv_bfloat16 g_qkvhi[(size_t)MROWS * 3 * HIDDEN]; // [4096][3072]
__device__ __align__(16) __nv_bfloat16 g_qkvlo[(size_t)MROWS * 3 * HIDDEN];
__device__ __align__(16) __nv_bfloat16 g_chi[(size_t)MROWS * HIDDEN];
__device__ __align__(16) __nv_bfloat16 g_clo[(size_t)MROWS * HIDDEN];
__device__ __align__(16) __nv_bfloat16 g_wqhi[(size_t)3 * HIDDEN * HIDDEN]; // [3072][1024] K-major
__device__ __align__(16) __nv_bfloat16 g_wqlo[(size_t)3 * HIDDEN * HIDDEN];
__device__ __align__(16) __nv_bfloat16 g_wohi[(size_t)HIDDEN * HIDDEN];     // [1024][1024] K-major
__device__ __align__(16) __nv_bfloat16 g_wolo[(size_t)HIDDEN * HIDDEN];

// ---------------------------------------------------------------------------
// mma.sync helpers (HMMA path — tcgen05 is unavailable: harness lowers via
// compute_103 PTX which rejects sm_103a-only instructions)
// ---------------------------------------------------------------------------
__device__ __forceinline__ void mma_bf16(float c[4],
                                         uint32_t a0, uint32_t a1, uint32_t a2, uint32_t a3,
                                         uint32_t b0, uint32_t b1) {
    asm volatile(
        "mma.sync.aligned.m16n8k16.row.col.f32.bf16.bf16.f32 "
        "{%0,%1,%2,%3}, {%4,%5,%6,%7}, {%8,%9}, {%0,%1,%2,%3};"
        : "+f"(c[0]), "+f"(c[1]), "+f"(c[2]), "+f"(c[3])
        : "r"(a0), "r"(a1), "r"(a2), "r"(a3), "r"(b0), "r"(b1));
}
__device__ __forceinline__ uint32_t pack_bf16(float x, float y) {
    __nv_bfloat162 t = __floats2bfloat162_rn(x, y);
    return *(uint32_t*)&t;
}
__device__ __forceinline__ uint32_t lds32(const __nv_bfloat16* p) {
    return *(const uint32_t*)p;
}

// ---------------------------------------------------------------------------
// Split fp32 x -> (bf16 hi, bf16 lo)
// ---------------------------------------------------------------------------
__global__ void __launch_bounds__(256) split_kernel(const float* __restrict__ in)
{
    size_t i = ((size_t)blockIdx.x * 256 + threadIdx.x) * 4;
    float4 v = *(const float4*)(in + i);
    __nv_bfloat16 h0 = __float2bfloat16(v.x), h1 = __float2bfloat16(v.y);
    __nv_bfloat16 h2 = __float2bfloat16(v.z), h3 = __float2bfloat16(v.w);
    __nv_bfloat16 l0 = __float2bfloat16(v.x - __bfloat162float(h0));
    __nv_bfloat16 l1 = __float2bfloat16(v.y - __bfloat162float(h1));
    __nv_bfloat16 l2 = __float2bfloat16(v.z - __bfloat162float(h2));
    __nv_bfloat16 l3 = __float2bfloat16(v.w - __bfloat162float(h3));
    *(__nv_bfloat162*)(g_xhi + i)     = __nv_bfloat162(h0, h1);
    *(__nv_bfloat162*)(g_xhi + i + 2) = __nv_bfloat162(h2, h3);
    *(__nv_bfloat162*)(g_xlo + i)     = __nv_bfloat162(l0, l1);
    *(__nv_bfloat162*)(g_xlo + i + 2) = __nv_bfloat162(l2, l3);
}

// ---------------------------------------------------------------------------
// Transpose+split weights: in[K][N] fp32 -> hi/lo [N][K] bf16 (K-major)
// ---------------------------------------------------------------------------
template <int MODE>
__global__ void __launch_bounds__(256) tsplit_kernel(const float* __restrict__ in,
                                                     int Kdim, int Ndim)
{
    __shared__ float tile[32][33];
    const int n0 = blockIdx.x * 32, k0 = blockIdx.y * 32;
    const int tx = threadIdx.x, ty = threadIdx.y;   // (32, 8)
    __nv_bfloat16* hi = (MODE == 0) ? g_wqhi : g_wohi;
    __nv_bfloat16* lo = (MODE == 0) ? g_wqlo : g_wolo;
#pragma unroll
    for (int i = 0; i < 32; i += 8)
        tile[ty + i][tx] = in[(size_t)(k0 + ty + i) * Ndim + n0 + tx];
    __syncthreads();
#pragma unroll
    for (int i = 0; i < 32; i += 8) {
        float v = tile[tx][ty + i];
        __nv_bfloat16 h = __float2bfloat16(v);
        __nv_bfloat16 l = __float2bfloat16(v - __bfloat162float(h));
        size_t o = (size_t)(n0 + ty + i) * Kdim + k0 + tx;
        hi[o] = h;
        lo[o] = l;
    }
}

// ---------------------------------------------------------------------------
// bf16-split HMMA GEMM + bias: C[M, N] = A[M,1024] @ B[N,1024]^T + bias[N]
// 128x128 tile / CTA, BK=32, 8 warps (4x2), warp tile 32x64.
// MODE 0: A = g_xhi/lo, B = g_wqhi/lo, out -> g_qkvhi/lo (bf16 split, +bias)
// MODE 1: A = g_chi/lo, B = g_wohi/lo, out -> fp32 Cext (+bias)
// ---------------------------------------------------------------------------
template <int MODE>
__global__ void __launch_bounds__(256) gemm_hmma_kernel(
    const float* __restrict__ bias, float* __restrict__ Cext, int N)
{
    constexpr int K = 1024;
    constexpr int SA = 40;                 // smem row stride (bf16) for 32-col tile
    __shared__ __nv_bfloat16 Ah[128 * SA], Al[128 * SA];
    __shared__ __nv_bfloat16 Bh[128 * SA], Bl[128 * SA];

    const __nv_bfloat16* Ahi = (MODE == 0) ? g_xhi : g_chi;
    const __nv_bfloat16* Alo = (MODE == 0) ? g_xlo : g_clo;
    const __nv_bfloat16* Bhi = (MODE == 0) ? g_wqhi : g_wohi;
    const __nv_bfloat16* Blo = (MODE == 0) ? g_wqlo : g_wolo;

    const int tid = threadIdx.x;
    const int wid = tid >> 5, lane = tid & 31;
    const int g = lane >> 2, t2 = (lane & 3) * 2;
    const int warp_m = (wid >> 1) * 32;      // 0,32,64,96
    const int warp_n = (wid & 1) * 64;       // 0,64
    const int rowBase = blockIdx.y * 128, colBase = blockIdx.x * 128;

    float c[2][8][4];
#pragma unroll
    for (int mt = 0; mt < 2; mt++)
#pragma unroll
        for (int nt = 0; nt < 8; nt++)
#pragma unroll
            for (int j = 0; j < 4; j++) c[mt][nt][j] = 0.0f;

    for (int k0 = 0; k0 < K; k0 += 32) {
        // load A/B tiles (128 rows x 32 cols each, hi+lo)
#pragma unroll
        for (int t = 0; t < 4; t++) {
            int i = tid + t * 256;           // 1024 chunks of 4 elems
            int row = i >> 3;
            int c4 = (i & 7) * 4;
            size_t ga = (size_t)(rowBase + row) * K + k0 + c4;
            size_t gb = (size_t)(colBase + row) * K + k0 + c4;
            *(uint2*)&Ah[row * SA + c4] = *(const uint2*)(Ahi + ga);
            *(uint2*)&Al[row * SA + c4] = *(const uint2*)(Alo + ga);
            *(uint2*)&Bh[row * SA + c4] = *(const uint2*)(Bhi + gb);
            *(uint2*)&Bl[row * SA + c4] = *(const uint2*)(Blo + gb);
        }
        __syncthreads();

#pragma unroll
        for (int kk = 0; kk < 32; kk += 16) {
            // a-frags for both m-tiles (hi & lo)
            uint32_t ah[2][4], al[2][4];
#pragma unroll
            for (int mt = 0; mt < 2; mt++) {
                int r0 = (warp_m + mt * 16 + g) * SA;
                int r1 = (warp_m + mt * 16 + g + 8) * SA;
                ah[mt][0] = lds32(&Ah[r0 + kk + t2]);
                ah[mt][1] = lds32(&Ah[r1 + kk + t2]);
                ah[mt][2] = lds32(&Ah[r0 + kk + 8 + t2]);
                ah[mt][3] = lds32(&Ah[r1 + kk + 8 + t2]);
                al[mt][0] = lds32(&Al[r0 + kk + t2]);
                al[mt][1] = lds32(&Al[r1 + kk + t2]);
                al[mt][2] = lds32(&Al[r0 + kk + 8 + t2]);
                al[mt][3] = lds32(&Al[r1 + kk + 8 + t2]);
            }
#pragma unroll
            for (int nt = 0; nt < 8; nt++) {
                int nr = (warp_n + nt * 8 + g) * SA;
                uint32_t bh0 = lds32(&Bh[nr + kk + t2]);
                uint32_t bh1 = lds32(&Bh[nr + kk + 8 + t2]);
                uint32_t bl0 = lds32(&Bl[nr + kk + t2]);
                uint32_t bl1 = lds32(&Bl[nr + kk + 8 + t2]);
#pragma unroll
                for (int mt = 0; mt < 2; mt++) {
                    mma_bf16(c[mt][nt], ah[mt][0], ah[mt][1], ah[mt][2], ah[mt][3], bh0, bh1);
                    mma_bf16(c[mt][nt], ah[mt][0], ah[mt][1], ah[mt][2], ah[mt][3], bl0, bl1);
                    mma_bf16(c[mt][nt], al[mt][0], al[mt][1], al[mt][2], al[mt][3], bh0, bh1);
                }
            }
        }
        __syncthreads();
    }

    // epilogue
#pragma unroll
    for (int mt = 0; mt < 2; mt++) {
        int row0 = rowBase + warp_m + mt * 16 + g;
        int row1 = row0 + 8;
#pragma unroll
        for (int nt = 0; nt < 8; nt++) {
            int col = colBase + warp_n + nt * 8 + t2;
            float b0 = bias[col], b1 = bias[col + 1];
            float v00 = c[mt][nt][0] + b0, v01 = c[mt][nt][1] + b1;
            float v10 = c[mt][nt][2] + b0, v11 = c[mt][nt][3] + b1;
            if (MODE == 0) {
                __nv_bfloat16 h00 = __float2bfloat16(v00), h01 = __float2bfloat16(v01);
                __nv_bfloat16 h10 = __float2bfloat16(v10), h11 = __float2bfloat16(v11);
                size_t o0 = (size_t)row0 * N + col, o1 = (size_t)row1 * N + col;
                *(__nv_bfloat162*)(g_qkvhi + o0) = __nv_bfloat162(h00, h01);
                *(__nv_bfloat162*)(g_qkvhi + o1) = __nv_bfloat162(h10, h11);
                *(__nv_bfloat162*)(g_qkvlo + o0) = __nv_bfloat162(
                    __float2bfloat16(v00 - __bfloat162float(h00)),
                    __float2bfloat16(v01 - __bfloat162float(h01)));
                *(__nv_bfloat162*)(g_qkvlo + o1) = __nv_bfloat162(
                    __float2bfloat16(v10 - __bfloat162float(h10)),
                    __float2bfloat16(v11 - __bfloat162float(h11)));
            } else {
                *(float2*)(Cext + (size_t)row0 * N + col) = make_float2(v00, v01);
                *(float2*)(Cext + (size_t)row1 * N + col) = make_float2(v10, v11);
            }
        }
    }
}

// ---------------------------------------------------------------------------
// Flash attention on HMMA. Br=128 q-rows/CTA, Bc=64 kv/iter, 8 warps, each
// warp owns a m16 row-slab. RoPE elided (head-indexed tables -> per-head
// constant orthogonal rotation of both q and k -> scores unchanged).
// S and PV use bf16 hi/lo 3-term splits; P packs c-frags directly to a-frags.
// Writes ctx as bf16 hi/lo for the out-projection.
// ---------------------------------------------------------------------------
__global__ void __launch_bounds__(256) attn_hmma_kernel()
{
    constexpr int SK = 72;   // smem row stride for 64-wide tiles
    __shared__ __nv_bfloat16 Kh[64 * SK], Kl[64 * SK];
    __shared__ __nv_bfloat16 Vth[64 * SK], Vtl[64 * SK];

    const int bh = blockIdx.x;       // b*16+h
    const int b  = bh >> 4, h = bh & 15;
    const int q0 = blockIdx.y * 128;
    const int tid = threadIdx.x;
    const int w = tid >> 5, lane = tid & 31;
    const int g = lane >> 2, t2 = (lane & 3) * 2;

    const int qcol = h * 192, kcol = qcol + 64, vcol = qcol + 128;
    const size_t tokBase = (size_t)b * SEQ;

    // Preload Q a-frags from gmem (rows q0 + w*16 + {g, g+8}, d chunks kk*16)
    uint32_t qh[4][4], ql[4][4];
    {
        const size_t r0 = (tokBase + q0 + w * 16 + g) * 3072 + qcol;
        const size_t r1 = r0 + (size_t)8 * 3072;
#pragma unroll
        for (int kk = 0; kk < 4; kk++) {
            int cc = kk * 16 + t2;
            qh[kk][0] = lds32(g_qkvhi + r0 + cc);
            qh[kk][1] = lds32(g_qkvhi + r1 + cc);
            qh[kk][2] = lds32(g_qkvhi + r0 + cc + 8);
            qh[kk][3] = lds32(g_qkvhi + r1 + cc + 8);
            ql[kk][0] = lds32(g_qkvlo + r0 + cc);
            ql[kk][1] = lds32(g_qkvlo + r1 + cc);
            ql[kk][2] = lds32(g_qkvlo + r0 + cc + 8);
            ql[kk][3] = lds32(g_qkvlo + r1 + cc + 8);
        }
    }

    float o[8][4];
#pragma unroll
    for (int nt = 0; nt < 8; nt++)
#pragma unroll
        for (int j = 0; j < 4; j++) o[nt][j] = 0.0f;
    float m0 = -INFINITY, m1 = -INFINITY, l0 = 0.0f, l1 = 0.0f;

    for (int kv0 = 0; kv0 < SEQ; kv0 += 64) {
        // load K tile [64][64] hi/lo (natural) and V tile transposed -> Vt[d][kv]
#pragma unroll
        for (int t = 0; t < 4; t++) {
            int i = tid + t * 256;          // 1024 chunks of 4
            int row = i >> 4;               // kv row 0..63
            int c4 = (i & 15) * 4;          // d 0..60
            size_t gk = (tokBase + kv0 + row) * 3072 + kcol + c4;
            size_t gv = (tokBase + kv0 + row) * 3072 + vcol + c4;
            *(uint2*)&Kh[row * SK + c4] = *(const uint2*)(g_qkvhi + gk);
            *(uint2*)&Kl[row * SK + c4] = *(const uint2*)(g_qkvlo + gk);
            uint2 vh = *(const uint2*)(g_qkvhi + gv);
            uint2 vl = *(const uint2*)(g_qkvlo + gv);
            const __nv_bfloat16* ph = (const __nv_bfloat16*)&vh;
            const __nv_bfloat16* pl = (const __nv_bfloat16*)&vl;
#pragma unroll
            for (int j = 0; j < 4; j++) {
                Vth[(c4 + j) * SK + row] = ph[j];
                Vtl[(c4 + j) * SK + row] = pl[j];
            }
        }
        __syncthreads();

        // S = Q K^T  (warp rows m16, cols kv 0..63 in 8 n-tiles)
        float s[8][4];
#pragma unroll
        for (int nt = 0; nt < 8; nt++) {
#pragma unroll
            for (int j = 0; j < 4; j++) s[nt][j] = 0.0f;
            int nr = (nt * 8 + g) * SK;
#pragma unroll
            for (int kk = 0; kk < 4; kk++) {
                int cc = kk * 16 + t2;
                uint32_t bh0 = lds32(&Kh[nr + cc]);
                uint32_t bh1 = lds32(&Kh[nr + cc + 8]);
                uint32_t bl0 = lds32(&Kl[nr + cc]);
                uint32_t bl1 = lds32(&Kl[nr + cc + 8]);
                mma_bf16(s[nt], qh[kk][0], qh[kk][1], qh[kk][2], qh[kk][3], bh0, bh1);
                mma_bf16(s[nt], qh[kk][0], qh[kk][1], qh[kk][2], qh[kk][3], bl0, bl1);
                mma_bf16(s[nt], ql[kk][0], ql[kk][1], ql[kk][2], ql[kk][3], bh0, bh1);
            }
        }

        // online softmax (rows g and g+8; 4 lanes/row -> shfl width 4)
        float mt0 = -INFINITY, mt1 = -INFINITY;
#pragma unroll
        for (int nt = 0; nt < 8; nt++) {
#pragma unroll
            for (int j = 0; j < 4; j++) s[nt][j] *= 0.125f;
            mt0 = fmaxf(mt0, fmaxf(s[nt][0], s[nt][1]));
            mt1 = fmaxf(mt1, fmaxf(s[nt][2], s[nt][3]));
        }
        mt0 = fmaxf(mt0, __shfl_xor_sync(0xffffffffu, mt0, 1, 4));
        mt0 = fmaxf(mt0, __shfl_xor_sync(0xffffffffu, mt0, 2, 4));
        mt1 = fmaxf(mt1, __shfl_xor_sync(0xffffffffu, mt1, 1, 4));
        mt1 = fmaxf(mt1, __shfl_xor_sync(0xffffffffu, mt1, 2, 4));
        float mn0 = fmaxf(m0, mt0), mn1 = fmaxf(m1, mt1);
        float a0 = __expf(m0 - mn0), a1 = __expf(m1 - mn1);
        float ls0 = 0.0f, ls1 = 0.0f;
#pragma unroll
        for (int nt = 0; nt < 8; nt++) {
            s[nt][0] = __expf(s[nt][0] - mn0);
            s[nt][1] = __expf(s[nt][1] - mn0);
            s[nt][2] = __expf(s[nt][2] - mn1);
            s[nt][3] = __expf(s[nt][3] - mn1);
            ls0 += s[nt][0] + s[nt][1];
            ls1 += s[nt][2] + s[nt][3];
        }
        ls0 += __shfl_xor_sync(0xffffffffu, ls0, 1, 4);
        ls0 += __shfl_xor_sync(0xffffffffu, ls0, 2, 4);
        ls1 += __shfl_xor_sync(0xffffffffu, ls1, 1, 4);
        ls1 += __shfl_xor_sync(0xffffffffu, ls1, 2, 4);
        l0 = l0 * a0 + ls0;
        l1 = l1 * a1 + ls1;
        m0 = mn0;
        m1 = mn1;
#pragma unroll
        for (int nt = 0; nt < 8; nt++) {
            o[nt][0] *= a0;
            o[nt][1] *= a0;
            o[nt][2] *= a1;
            o[nt][3] *= a1;
        }

        // P -> a-frags (hi/lo), c-frag -> a-frag identity
        uint32_t ph[4][4], pl[4][4];
#pragma unroll
        for (int kt = 0; kt < 4; kt++) {
            float p00 = s[kt * 2][0],     p01 = s[kt * 2][1];
            float p10 = s[kt * 2][2],     p11 = s[kt * 2][3];
            float p20 = s[kt * 2 + 1][0], p21 = s[kt * 2 + 1][1];
            float p30 = s[kt * 2 + 1][2], p31 = s[kt * 2 + 1][3];
            ph[kt][0] = pack_bf16(p00, p01);
            ph[kt][1] = pack_bf16(p10, p11);
            ph[kt][2] = pack_bf16(p20, p21);
            ph[kt][3] = pack_bf16(p30, p31);
            const __nv_bfloat162* hp;
            hp = (const __nv_bfloat162*)&ph[kt][0];
            pl[kt][0] = pack_bf16(p00 - __bfloat162float(hp->x), p01 - __bfloat162float(hp->y));
            hp = (const __nv_bfloat162*)&ph[kt][1];
            pl[kt][1] = pack_bf16(p10 - __bfloat162float(hp->x), p11 - __bfloat162float(hp->y));
            hp = (const __nv_bfloat162*)&ph[kt][2];
            pl[kt][2] = pack_bf16(p20 - __bfloat162float(hp->x), p21 - __bfloat162float(hp->y));
            hp = (const __nv_bfloat162*)&ph[kt][3];
            pl[kt][3] = pack_bf16(p30 - __bfloat162float(hp->x), p31 - __bfloat162float(hp->y));
        }

        // O += P V   (n-dim = d, k-dim = kv; B from Vt)
#pragma unroll
        for (int nt = 0; nt < 8; nt++) {
            int nr = (nt * 8 + g) * SK;
#pragma unroll
            for (int kt = 0; kt < 4; kt++) {
                int cc = kt * 16 + t2;
                uint32_t bh0 = lds32(&Vth[nr + cc]);
                uint32_t bh1 = lds32(&Vth[nr + cc + 8]);
                uint32_t bl0 = lds32(&Vtl[nr + cc]);
                uint32_t bl1 = lds32(&Vtl[nr + cc + 8]);
                mma_bf16(o[nt], ph[kt][0], ph[kt][1], ph[kt][2], ph[kt][3], bh0, bh1);
                mma_bf16(o[nt], ph[kt][0], ph[kt][1], ph[kt][2], ph[kt][3], bl0, bl1);
                mma_bf16(o[nt], pl[kt][0], pl[kt][1], pl[kt][2], pl[kt][3], bh0, bh1);
            }
        }
        __syncthreads();
    }

    // epilogue: normalize, split to bf16 hi/lo, write ctx[token][h*64+d]
    const float i0 = 1.0f / l0, i1 = 1.0f / l1;
    const size_t c0 = (tokBase + q0 + w * 16 + g) * HIDDEN + h * HD;
    const size_t c1 = c0 + (size_t)8 * HIDDEN;
#pragma unroll
    for (int nt = 0; nt < 8; nt++) {
        int d = nt * 8 + t2;
        float v00 = o[nt][0] * i0, v01 = o[nt][1] * i0;
        float v10 = o[nt][2] * i1, v11 = o[nt][3] * i1;
        __nv_bfloat16 h00 = __float2bfloat16(v00), h01 = __float2bfloat16(v01);
        __nv_bfloat16 h10 = __float2bfloat16(v10), h11 = __float2bfloat16(v11);
        *(__nv_bfloat162*)(g_chi + c0 + d) = __nv_bfloat162(h00, h01);
        *(__nv_bfloat162*)(g_chi + c1 + d) = __nv_bfloat162(h10, h11);
        *(__nv_bfloat162*)(g_clo + c0 + d) = __nv_bfloat162(
            __float2bfloat16(v00 - __bfloat162float(h00)),
            __float2bfloat16(v01 - __bfloat162float(h01)));
        *(__nv_bfloat162*)(g_clo + c1 + d) = __nv_bfloat162(
            __float2bfloat16(v10 - __bfloat162float(h10)),
            __float2bfloat16(v11 - __bfloat162float(h11)));
    }
}

// ---------------------------------------------------------------------------
extern "C" void kernel_launch(void* const* d_in, const int* in_sizes, int n_in,
                              void* d_out, int out_size)
{
    (void)in_sizes; (void)n_in; (void)out_size;
    const float* x     = (const float*)d_in[0];
    const float* qkv_w = (const float*)d_in[1];
    const float* qkv_b = (const float*)d_in[2];
    const float* out_w = (const float*)d_in[3];
    const float* out_b = (const float*)d_in[4];
    float* out = (float*)d_out;

    // 0) splits: weights (transpose to K-major) + activations
    tsplit_kernel<0><<<dim3(3 * HIDDEN / 32, HIDDEN / 32), dim3(32, 8)>>>(qkv_w, HIDDEN, 3 * HIDDEN);
    tsplit_kernel<1><<<dim3(HIDDEN / 32, HIDDEN / 32), dim3(32, 8)>>>(out_w, HIDDEN, HIDDEN);
    split_kernel<<<(MROWS * HIDDEN) / (256 * 4), 256>>>(x);

    // 1) QKV projection -> bf16 hi/lo qkv
    gemm_hmma_kernel<0><<<dim3(3 * HIDDEN / 128, MROWS / 128), 256>>>(
        qkv_b, nullptr, 3 * HIDDEN);

    // 2) Flash attention (HMMA) -> bf16 hi/lo ctx
    attn_hmma_kernel<<<dim3(BATCH * HEADS, SEQ / 128), 256>>>();

    // 3) Output projection -> fp32 out
    gemm_hmma_kernel<1><<<dim3(HIDDEN / 128, MROWS / 128), 256>>>(
        out_b, out, HIDDEN);
}

// round 10
// speedup vs baseline: 2.6261x; 1.3245x over previous
#include <cuda_runtime.h>
#include <cuda_bf16.h>
#include <math.h>
#include <stdint.h>

#define HIDDEN 1024
#define SEQ    2048
#define BATCH  2
#define HEADS  16
#define HD     64
#define MROWS  (BATCH * SEQ)   /* 4096 */

// ---------------------------------------------------------------------------
// Scratch (device globals — no allocation allowed)
// ---------------------------------------------------------------------------
__device__ __align__(16) __nv_bfloat16 g_xhi[(size_t)MROWS * HIDDEN];
__device__ __align__(16) __nv_bfloat16 g_xlo[(size_t)MROWS * HIDDEN];
__device__ __align__(16) __nv_bfloat16 g_qkvhi[(size_t)MROWS * 3 * HIDDEN]; // [4096][3072]
__device__ __align__(16) __nv_bfloat16 g_qkvlo[(size_t)MROWS * 3 * HIDDEN];
__device__ __align__(16) __nv_bfloat16 g_chi[(size_t)MROWS * HIDDEN];
__device__ __align__(16) __nv_bfloat16 g_clo[(size_t)MROWS * HIDDEN];
__device__ __align__(16) __nv_bfloat16 g_wqhi[(size_t)3 * HIDDEN * HIDDEN]; // [3072][1024] K-major
__device__ __align__(16) __nv_bfloat16 g_wqlo[(size_t)3 * HIDDEN * HIDDEN];
__device__ __align__(16) __nv_bfloat16 g_wohi[(size_t)HIDDEN * HIDDEN];     // [1024][1024] K-major
__device__ __align__(16) __nv_bfloat16 g_wolo[(size_t)HIDDEN * HIDDEN];

// ---------------------------------------------------------------------------
// helpers
// ---------------------------------------------------------------------------
__device__ __forceinline__ void mma_bf16(float c[4],
                                         uint32_t a0, uint32_t a1, uint32_t a2, uint32_t a3,
                                         uint32_t b0, uint32_t b1) {
    asm volatile(
        "mma.sync.aligned.m16n8k16.row.col.f32.bf16.bf16.f32 "
        "{%0,%1,%2,%3}, {%4,%5,%6,%7}, {%8,%9}, {%0,%1,%2,%3};"
        : "+f"(c[0]), "+f"(c[1]), "+f"(c[2]), "+f"(c[3])
        : "r"(a0), "r"(a1), "r"(a2), "r"(a3), "r"(b0), "r"(b1));
}
__device__ __forceinline__ uint32_t pack_bf16(float x, float y) {
    __nv_bfloat162 t = __floats2bfloat162_rn(x, y);
    return *(uint32_t*)&t;
}
__device__ __forceinline__ uint32_t lds32(const __nv_bfloat16* p) {
    return *(const uint32_t*)p;
}
__device__ __forceinline__ uint32_t smem_u32(const void* p) {
    uint32_t a;
    asm("{ .reg .u64 t; cvta.to.shared.u64 t, %1; cvt.u32.u64 %0, t; }" : "=r"(a) : "l"(p));
    return a;
}
__device__ __forceinline__ void cpa16(const __nv_bfloat16* s, const __nv_bfloat16* g) {
    uint32_t sa = smem_u32(s);
    asm volatile("cp.async.cg.shared.global [%0], [%1], 16;" :: "r"(sa), "l"(g) : "memory");
}
#define CP_COMMIT() asm volatile("cp.async.commit_group;" ::: "memory")
#define CP_WAIT(n)  asm volatile("cp.async.wait_group %0;" :: "n"(n) : "memory")
// ldmatrix x4 transposed (b16): B-frags from row-major [k][n] memory
__device__ __forceinline__ void ldmx4t(uint32_t& r0, uint32_t& r1, uint32_t& r2, uint32_t& r3,
                                       uint32_t addr) {
    asm volatile("ldmatrix.sync.aligned.m8n8.x4.trans.shared.b16 {%0,%1,%2,%3}, [%4];"
                 : "=r"(r0), "=r"(r1), "=r"(r2), "=r"(r3) : "r"(addr));
}

// ---------------------------------------------------------------------------
// Split fp32 x -> (bf16 hi, bf16 lo)
// ---------------------------------------------------------------------------
__global__ void __launch_bounds__(256) split_kernel(const float* __restrict__ in)
{
    size_t i = ((size_t)blockIdx.x * 256 + threadIdx.x) * 4;
    float4 v = *(const float4*)(in + i);
    __nv_bfloat16 h0 = __float2bfloat16(v.x), h1 = __float2bfloat16(v.y);
    __nv_bfloat16 h2 = __float2bfloat16(v.z), h3 = __float2bfloat16(v.w);
    __nv_bfloat16 l0 = __float2bfloat16(v.x - __bfloat162float(h0));
    __nv_bfloat16 l1 = __float2bfloat16(v.y - __bfloat162float(h1));
    __nv_bfloat16 l2 = __float2bfloat16(v.z - __bfloat162float(h2));
    __nv_bfloat16 l3 = __float2bfloat16(v.w - __bfloat162float(h3));
    *(__nv_bfloat162*)(g_xhi + i)     = __nv_bfloat162(h0, h1);
    *(__nv_bfloat162*)(g_xhi + i + 2) = __nv_bfloat162(h2, h3);
    *(__nv_bfloat162*)(g_xlo + i)     = __nv_bfloat162(l0, l1);
    *(__nv_bfloat162*)(g_xlo + i + 2) = __nv_bfloat162(l2, l3);
}

// ---------------------------------------------------------------------------
// Transpose+split weights: in[K][N] fp32 -> hi/lo [N][K] bf16 (K-major)
// ---------------------------------------------------------------------------
template <int MODE>
__global__ void __launch_bounds__(256) tsplit_kernel(const float* __restrict__ in,
                                                     int Kdim, int Ndim)
{
    __shared__ float tile[32][33];
    const int n0 = blockIdx.x * 32, k0 = blockIdx.y * 32;
    const int tx = threadIdx.x, ty = threadIdx.y;   // (32, 8)
    __nv_bfloat16* hi = (MODE == 0) ? g_wqhi : g_wohi;
    __nv_bfloat16* lo = (MODE == 0) ? g_wqlo : g_wolo;
#pragma unroll
    for (int i = 0; i < 32; i += 8)
        tile[ty + i][tx] = in[(size_t)(k0 + ty + i) * Ndim + n0 + tx];
    __syncthreads();
#pragma unroll
    for (int i = 0; i < 32; i += 8) {
        float v = tile[tx][ty + i];
        __nv_bfloat16 h = __float2bfloat16(v);
        __nv_bfloat16 l = __float2bfloat16(v - __bfloat162float(h));
        size_t o = (size_t)(n0 + ty + i) * Kdim + k0 + tx;
        hi[o] = h;
        lo[o] = l;
    }
}

// ---------------------------------------------------------------------------
// bf16-split HMMA GEMM + bias, 2-stage cp.async pipeline.
// C[M,N] = A[M,1024] @ B[N,1024]^T + bias[N]; 128x128 tile, BK=32, 8 warps.
// MODE 0: A=g_xhi/lo, B=g_wqhi/lo -> g_qkvhi/lo (+bias, bf16 split)
// MODE 1: A=g_chi/lo, B=g_wohi/lo -> fp32 Cext (+bias)
// ---------------------------------------------------------------------------
template <int MODE>
__global__ void __launch_bounds__(256, 2) gemm_hmma_kernel(
    const float* __restrict__ bias, float* __restrict__ Cext, int N)
{
    constexpr int K = 1024;
    constexpr int SA = 40;               // smem row stride (elems); 80B, 16B-aligned
    constexpr int TS = 128 * SA;         // elems per tile
    extern __shared__ __nv_bfloat16 dsm[];  // [2 stages][Ah|Al|Bh|Bl]

    const __nv_bfloat16* Ahi = (MODE == 0) ? g_xhi : g_chi;
    const __nv_bfloat16* Alo = (MODE == 0) ? g_xlo : g_clo;
    const __nv_bfloat16* Bhi = (MODE == 0) ? g_wqhi : g_wohi;
    const __nv_bfloat16* Blo = (MODE == 0) ? g_wqlo : g_wolo;

    const int tid = threadIdx.x;
    const int wid = tid >> 5, lane = tid & 31;
    const int g = lane >> 2, t2 = (lane & 3) * 2;
    const int warp_m = (wid >> 1) * 32;
    const int warp_n = (wid & 1) * 64;
    const int rowBase = blockIdx.y * 128, colBase = blockIdx.x * 128;

    // per-thread load coords: 2 chunks of 16B per tile
    const int lrow0 = tid >> 2, lc0 = (tid & 3) * 8;          // chunk 0: rows 0..63
    const int lrow1 = (tid + 256) >> 2, lc1 = lc0;            // chunk 1: rows 64..127

    float c[2][8][4];
#pragma unroll
    for (int mt = 0; mt < 2; mt++)
#pragma unroll
        for (int nt = 0; nt < 8; nt++)
#pragma unroll
            for (int j = 0; j < 4; j++) c[mt][nt][j] = 0.0f;

    auto load_stage = [&](int st, int k0) {
        __nv_bfloat16* s = dsm + st * 4 * TS;
        size_t ga0 = (size_t)(rowBase + lrow0) * K + k0 + lc0;
        size_t ga1 = (size_t)(rowBase + lrow1) * K + k0 + lc1;
        size_t gb0 = (size_t)(colBase + lrow0) * K + k0 + lc0;
        size_t gb1 = (size_t)(colBase + lrow1) * K + k0 + lc1;
        cpa16(s + lrow0 * SA + lc0, Ahi + ga0);
        cpa16(s + lrow1 * SA + lc1, Ahi + ga1);
        cpa16(s + TS + lrow0 * SA + lc0, Alo + ga0);
        cpa16(s + TS + lrow1 * SA + lc1, Alo + ga1);
        cpa16(s + 2 * TS + lrow0 * SA + lc0, Bhi + gb0);
        cpa16(s + 2 * TS + lrow1 * SA + lc1, Bhi + gb1);
        cpa16(s + 3 * TS + lrow0 * SA + lc0, Blo + gb0);
        cpa16(s + 3 * TS + lrow1 * SA + lc1, Blo + gb1);
        CP_COMMIT();
    };

    load_stage(0, 0);

    for (int it = 0; it < K / 32; ++it) {
        const int cur = it & 1;
        if (it + 1 < K / 32) {
            load_stage(cur ^ 1, (it + 1) * 32);
            CP_WAIT(1);
        } else {
            CP_WAIT(0);
        }
        __syncthreads();

        const __nv_bfloat16* sAh = dsm + cur * 4 * TS;
        const __nv_bfloat16* sAl = sAh + TS;
        const __nv_bfloat16* sBh = sAh + 2 * TS;
        const __nv_bfloat16* sBl = sAh + 3 * TS;

#pragma unroll
        for (int kk = 0; kk < 32; kk += 16) {
            uint32_t ah[2][4], al[2][4];
#pragma unroll
            for (int mt = 0; mt < 2; mt++) {
                int r0 = (warp_m + mt * 16 + g) * SA;
                int r1 = (warp_m + mt * 16 + g + 8) * SA;
                ah[mt][0] = lds32(&sAh[r0 + kk + t2]);
                ah[mt][1] = lds32(&sAh[r1 + kk + t2]);
                ah[mt][2] = lds32(&sAh[r0 + kk + 8 + t2]);
                ah[mt][3] = lds32(&sAh[r1 + kk + 8 + t2]);
                al[mt][0] = lds32(&sAl[r0 + kk + t2]);
                al[mt][1] = lds32(&sAl[r1 + kk + t2]);
                al[mt][2] = lds32(&sAl[r0 + kk + 8 + t2]);
                al[mt][3] = lds32(&sAl[r1 + kk + 8 + t2]);
            }
#pragma unroll
            for (int nt = 0; nt < 8; nt++) {
                int nr = (warp_n + nt * 8 + g) * SA;
                uint32_t bh0 = lds32(&sBh[nr + kk + t2]);
                uint32_t bh1 = lds32(&sBh[nr + kk + 8 + t2]);
                uint32_t bl0 = lds32(&sBl[nr + kk + t2]);
                uint32_t bl1 = lds32(&sBl[nr + kk + 8 + t2]);
#pragma unroll
                for (int mt = 0; mt < 2; mt++) {
                    mma_bf16(c[mt][nt], ah[mt][0], ah[mt][1], ah[mt][2], ah[mt][3], bh0, bh1);
                    mma_bf16(c[mt][nt], ah[mt][0], ah[mt][1], ah[mt][2], ah[mt][3], bl0, bl1);
                    mma_bf16(c[mt][nt], al[mt][0], al[mt][1], al[mt][2], al[mt][3], bh0, bh1);
                }
            }
        }
        __syncthreads();
    }

    // epilogue
#pragma unroll
    for (int mt = 0; mt < 2; mt++) {
        int row0 = rowBase + warp_m + mt * 16 + g;
        int row1 = row0 + 8;
#pragma unroll
        for (int nt = 0; nt < 8; nt++) {
            int col = colBase + warp_n + nt * 8 + t2;
            float b0 = bias[col], b1 = bias[col + 1];
            float v00 = c[mt][nt][0] + b0, v01 = c[mt][nt][1] + b1;
            float v10 = c[mt][nt][2] + b0, v11 = c[mt][nt][3] + b1;
            if (MODE == 0) {
                __nv_bfloat16 h00 = __float2bfloat16(v00), h01 = __float2bfloat16(v01);
                __nv_bfloat16 h10 = __float2bfloat16(v10), h11 = __float2bfloat16(v11);
                size_t o0 = (size_t)row0 * N + col, o1 = (size_t)row1 * N + col;
                *(__nv_bfloat162*)(g_qkvhi + o0) = __nv_bfloat162(h00, h01);
                *(__nv_bfloat162*)(g_qkvhi + o1) = __nv_bfloat162(h10, h11);
                *(__nv_bfloat162*)(g_qkvlo + o0) = __nv_bfloat162(
                    __float2bfloat16(v00 - __bfloat162float(h00)),
                    __float2bfloat16(v01 - __bfloat162float(h01)));
                *(__nv_bfloat162*)(g_qkvlo + o1) = __nv_bfloat162(
                    __float2bfloat16(v10 - __bfloat162float(h10)),
                    __float2bfloat16(v11 - __bfloat162float(h11)));
            } else {
                *(float2*)(Cext + (size_t)row0 * N + col) = make_float2(v00, v01);
                *(float2*)(Cext + (size_t)row1 * N + col) = make_float2(v10, v11);
            }
        }
    }
}

// ---------------------------------------------------------------------------
// Flash attention on HMMA, 2-stage cp.async pipeline, ldmatrix.trans for V.
// Br=128 q-rows/CTA, Bc=64 kv/iter, 8 warps x m16 row-slab. RoPE elided
// (head-indexed tables -> per-head constant orthogonal rotation of q and k).
// ---------------------------------------------------------------------------
__global__ void __launch_bounds__(256, 2) attn_hmma_kernel()
{
    constexpr int SK = 72;              // elems; 144B rows, 16B-aligned
    constexpr int KT = 64 * SK;         // elems per tile
    extern __shared__ __nv_bfloat16 dsm[];  // [2 stages][Kh|Kl|Vh|Vl]

    const int bh = blockIdx.x;
    const int b  = bh >> 4, h = bh & 15;
    const int q0 = blockIdx.y * 128;
    const int tid = threadIdx.x;
    const int w = tid >> 5, lane = tid & 31;
    const int g = lane >> 2, t2 = (lane & 3) * 2;

    const int qcol = h * 192, kcol = qcol + 64, vcol = qcol + 128;
    const size_t tokBase = (size_t)b * SEQ;

    // per-thread cp.async coords: 2 chunks of 16B per tile
    const int lrow0 = tid >> 3, lc0 = (tid & 7) * 8;          // rows 0..31
    const int lrow1 = (tid + 256) >> 3, lc1 = lc0;            // rows 32..63

    // ldmatrix.trans per-lane byte offset within V tile (k-seg, n-seg layout)
    const uint32_t vloff = ((((lane >> 3) & 1) * 8 + (lane & 7)) * SK + (lane >> 4) * 8) * 2;

    // Preload Q a-frags
    uint32_t qh[4][4], ql[4][4];
    {
        const size_t r0 = (tokBase + q0 + w * 16 + g) * 3072 + qcol;
        const size_t r1 = r0 + (size_t)8 * 3072;
#pragma unroll
        for (int kk = 0; kk < 4; kk++) {
            int cc = kk * 16 + t2;
            qh[kk][0] = lds32(g_qkvhi + r0 + cc);
            qh[kk][1] = lds32(g_qkvhi + r1 + cc);
            qh[kk][2] = lds32(g_qkvhi + r0 + cc + 8);
            qh[kk][3] = lds32(g_qkvhi + r1 + cc + 8);
            ql[kk][0] = lds32(g_qkvlo + r0 + cc);
            ql[kk][1] = lds32(g_qkvlo + r1 + cc);
            ql[kk][2] = lds32(g_qkvlo + r0 + cc + 8);
            ql[kk][3] = lds32(g_qkvlo + r1 + cc + 8);
        }
    }

    float o[8][4];
#pragma unroll
    for (int nt = 0; nt < 8; nt++)
#pragma unroll
        for (int j = 0; j < 4; j++) o[nt][j] = 0.0f;
    float m0 = -INFINITY, m1 = -INFINITY, l0 = 0.0f, l1 = 0.0f;

    auto load_stage = [&](int st, int kv0) {
        __nv_bfloat16* s = dsm + st * 4 * KT;
        size_t gk0 = (tokBase + kv0 + lrow0) * 3072 + kcol + lc0;
        size_t gk1 = (tokBase + kv0 + lrow1) * 3072 + kcol + lc1;
        size_t gv0 = (tokBase + kv0 + lrow0) * 3072 + vcol + lc0;
        size_t gv1 = (tokBase + kv0 + lrow1) * 3072 + vcol + lc1;
        cpa16(s + lrow0 * SK + lc0, g_qkvhi + gk0);
        cpa16(s + lrow1 * SK + lc1, g_qkvhi + gk1);
        cpa16(s + KT + lrow0 * SK + lc0, g_qkvlo + gk0);
        cpa16(s + KT + lrow1 * SK + lc1, g_qkvlo + gk1);
        cpa16(s + 2 * KT + lrow0 * SK + lc0, g_qkvhi + gv0);
        cpa16(s + 2 * KT + lrow1 * SK + lc1, g_qkvhi + gv1);
        cpa16(s + 3 * KT + lrow0 * SK + lc0, g_qkvlo + gv0);
        cpa16(s + 3 * KT + lrow1 * SK + lc1, g_qkvlo + gv1);
        CP_COMMIT();
    };

    load_stage(0, 0);

    for (int it = 0; it < SEQ / 64; ++it) {
        const int cur = it & 1;
        if (it + 1 < SEQ / 64) {
            load_stage(cur ^ 1, (it + 1) * 64);
            CP_WAIT(1);
        } else {
            CP_WAIT(0);
        }
        __syncthreads();

        const __nv_bfloat16* Kh = dsm + cur * 4 * KT;
        const __nv_bfloat16* Kl = Kh + KT;
        const uint32_t vh_base = smem_u32(Kh + 2 * KT) + vloff;
        const uint32_t vl_base = smem_u32(Kh + 3 * KT) + vloff;

        // S = Q K^T
        float s[8][4];
#pragma unroll
        for (int nt = 0; nt < 8; nt++) {
#pragma unroll
            for (int j = 0; j < 4; j++) s[nt][j] = 0.0f;
            int nr = (nt * 8 + g) * SK;
#pragma unroll
            for (int kk = 0; kk < 4; kk++) {
                int cc = kk * 16 + t2;
                uint32_t bh0 = lds32(&Kh[nr + cc]);
                uint32_t bh1 = lds32(&Kh[nr + cc + 8]);
                uint32_t bl0 = lds32(&Kl[nr + cc]);
                uint32_t bl1 = lds32(&Kl[nr + cc + 8]);
                mma_bf16(s[nt], qh[kk][0], qh[kk][1], qh[kk][2], qh[kk][3], bh0, bh1);
                mma_bf16(s[nt], qh[kk][0], qh[kk][1], qh[kk][2], qh[kk][3], bl0, bl1);
                mma_bf16(s[nt], ql[kk][0], ql[kk][1], ql[kk][2], ql[kk][3], bh0, bh1);
            }
        }

        // online softmax
        float mt0 = -INFINITY, mt1 = -INFINITY;
#pragma unroll
        for (int nt = 0; nt < 8; nt++) {
#pragma unroll
            for (int j = 0; j < 4; j++) s[nt][j] *= 0.125f;
            mt0 = fmaxf(mt0, fmaxf(s[nt][0], s[nt][1]));
            mt1 = fmaxf(mt1, fmaxf(s[nt][2], s[nt][3]));
        }
        mt0 = fmaxf(mt0, __shfl_xor_sync(0xffffffffu, mt0, 1, 4));
        mt0 = fmaxf(mt0, __shfl_xor_sync(0xffffffffu, mt0, 2, 4));
        mt1 = fmaxf(mt1, __shfl_xor_sync(0xffffffffu, mt1, 1, 4));
        mt1 = fmaxf(mt1, __shfl_xor_sync(0xffffffffu, mt1, 2, 4));
        float mn0 = fmaxf(m0, mt0), mn1 = fmaxf(m1, mt1);
        float a0 = __expf(m0 - mn0), a1 = __expf(m1 - mn1);
        float ls0 = 0.0f, ls1 = 0.0f;
#pragma unroll
        for (int nt = 0; nt < 8; nt++) {
            s[nt][0] = __expf(s[nt][0] - mn0);
            s[nt][1] = __expf(s[nt][1] - mn0);
            s[nt][2] = __expf(s[nt][2] - mn1);
            s[nt][3] = __expf(s[nt][3] - mn1);
            ls0 += s[nt][0] + s[nt][1];
            ls1 += s[nt][2] + s[nt][3];
        }
        ls0 += __shfl_xor_sync(0xffffffffu, ls0, 1, 4);
        ls0 += __shfl_xor_sync(0xffffffffu, ls0, 2, 4);
        ls1 += __shfl_xor_sync(0xffffffffu, ls1, 1, 4);
        ls1 += __shfl_xor_sync(0xffffffffu, ls1, 2, 4);
        l0 = l0 * a0 + ls0;
        l1 = l1 * a1 + ls1;
        m0 = mn0;
        m1 = mn1;
#pragma unroll
        for (int nt = 0; nt < 8; nt++) {
            o[nt][0] *= a0;
            o[nt][1] *= a0;
            o[nt][2] *= a1;
            o[nt][3] *= a1;
        }

        // P -> a-frags (hi/lo) via c-frag identity
        uint32_t ph[4][4], pl[4][4];
#pragma unroll
        for (int kt = 0; kt < 4; kt++) {
            float p00 = s[kt * 2][0],     p01 = s[kt * 2][1];
            float p10 = s[kt * 2][2],     p11 = s[kt * 2][3];
            float p20 = s[kt * 2 + 1][0], p21 = s[kt * 2 + 1][1];
            float p30 = s[kt * 2 + 1][2], p31 = s[kt * 2 + 1][3];
            ph[kt][0] = pack_bf16(p00, p01);
            ph[kt][1] = pack_bf16(p10, p11);
            ph[kt][2] = pack_bf16(p20, p21);
            ph[kt][3] = pack_bf16(p30, p31);
            const __nv_bfloat162* hp;
            hp = (const __nv_bfloat162*)&ph[kt][0];
            pl[kt][0] = pack_bf16(p00 - __bfloat162float(hp->x), p01 - __bfloat162float(hp->y));
            hp = (const __nv_bfloat162*)&ph[kt][1];
            pl[kt][1] = pack_bf16(p10 - __bfloat162float(hp->x), p11 - __bfloat162float(hp->y));
            hp = (const __nv_bfloat162*)&ph[kt][2];
            pl[kt][2] = pack_bf16(p20 - __bfloat162float(hp->x), p21 - __bfloat162float(hp->y));
            hp = (const __nv_bfloat162*)&ph[kt][3];
            pl[kt][3] = pack_bf16(p30 - __bfloat162float(hp->x), p31 - __bfloat162float(hp->y));
        }

        // O += P V : B-frags from natural V layout via ldmatrix.trans
        //   (k16, n16) per ldmatrix.x4: r0,r1 = n-block np*2, r2,r3 = np*2+1
#pragma unroll
        for (int np = 0; np < 4; np++) {
#pragma unroll
            for (int kt = 0; kt < 4; kt++) {
                uint32_t off = (uint32_t)((kt * 16 * SK + np * 16) * 2);
                uint32_t bh0, bh1, bh2, bh3, bl0, bl1, bl2, bl3;
                ldmx4t(bh0, bh1, bh2, bh3, vh_base + off);
                ldmx4t(bl0, bl1, bl2, bl3, vl_base + off);
                mma_bf16(o[np * 2], ph[kt][0], ph[kt][1], ph[kt][2], ph[kt][3], bh0, bh1);
                mma_bf16(o[np * 2], ph[kt][0], ph[kt][1], ph[kt][2], ph[kt][3], bl0, bl1);
                mma_bf16(o[np * 2], pl[kt][0], pl[kt][1], pl[kt][2], pl[kt][3], bh0, bh1);
                mma_bf16(o[np * 2 + 1], ph[kt][0], ph[kt][1], ph[kt][2], ph[kt][3], bh2, bh3);
                mma_bf16(o[np * 2 + 1], ph[kt][0], ph[kt][1], ph[kt][2], ph[kt][3], bl2, bl3);
                mma_bf16(o[np * 2 + 1], pl[kt][0], pl[kt][1], pl[kt][2], pl[kt][3], bh2, bh3);
            }
        }
        __syncthreads();
    }

    // epilogue: normalize, split to bf16 hi/lo, write ctx
    const float i0 = 1.0f / l0, i1 = 1.0f / l1;
    const size_t c0 = (tokBase + q0 + w * 16 + g) * HIDDEN + h * HD;
    const size_t c1 = c0 + (size_t)8 * HIDDEN;
#pragma unroll
    for (int nt = 0; nt < 8; nt++) {
        int d = nt * 8 + t2;
        float v00 = o[nt][0] * i0, v01 = o[nt][1] * i0;
        float v10 = o[nt][2] * i1, v11 = o[nt][3] * i1;
        __nv_bfloat16 h00 = __float2bfloat16(v00), h01 = __float2bfloat16(v01);
        __nv_bfloat16 h10 = __float2bfloat16(v10), h11 = __float2bfloat16(v11);
        *(__nv_bfloat162*)(g_chi + c0 + d) = __nv_bfloat162(h00, h01);
        *(__nv_bfloat162*)(g_chi + c1 + d) = __nv_bfloat162(h10, h11);
        *(__nv_bfloat162*)(g_clo + c0 + d) = __nv_bfloat162(
            __float2bfloat16(v00 - __bfloat162float(h00)),
            __float2bfloat16(v01 - __bfloat162float(h01)));
        *(__nv_bfloat162*)(g_clo + c1 + d) = __nv_bfloat162(
            __float2bfloat16(v10 - __bfloat162float(h10)),
            __float2bfloat16(v11 - __bfloat162float(h11)));
    }
}

// ---------------------------------------------------------------------------
extern "C" void kernel_launch(void* const* d_in, const int* in_sizes, int n_in,
                              void* d_out, int out_size)
{
    (void)in_sizes; (void)n_in; (void)out_size;
    const float* x     = (const float*)d_in[0];
    const float* qkv_w = (const float*)d_in[1];
    const float* qkv_b = (const float*)d_in[2];
    const float* out_w = (const float*)d_in[3];
    const float* out_b = (const float*)d_in[4];
    float* out = (float*)d_out;

    const int gemm_smem = 2 * 4 * 128 * 40 * 2;   // 81920 B
    const int attn_smem = 2 * 4 * 64 * 72 * 2;    // 73728 B
    cudaFuncSetAttribute(gemm_hmma_kernel<0>, cudaFuncAttributeMaxDynamicSharedMemorySize, gemm_smem);
    cudaFuncSetAttribute(gemm_hmma_kernel<1>, cudaFuncAttributeMaxDynamicSharedMemorySize, gemm_smem);
    cudaFuncSetAttribute(attn_hmma_kernel, cudaFuncAttributeMaxDynamicSharedMemorySize, attn_smem);

    // 0) splits
    tsplit_kernel<0><<<dim3(3 * HIDDEN / 32, HIDDEN / 32), dim3(32, 8)>>>(qkv_w, HIDDEN, 3 * HIDDEN);
    tsplit_kernel<1><<<dim3(HIDDEN / 32, HIDDEN / 32), dim3(32, 8)>>>(out_w, HIDDEN, HIDDEN);
    split_kernel<<<(MROWS * HIDDEN) / (256 * 4), 256>>>(x);

    // 1) QKV projection -> bf16 hi/lo qkv
    gemm_hmma_kernel<0><<<dim3(3 * HIDDEN / 128, MROWS / 128), 256, gemm_smem>>>(
        qkv_b, nullptr, 3 * HIDDEN);

    // 2) Flash attention -> bf16 hi/lo ctx
    attn_hmma_kernel<<<dim3(BATCH * HEADS, SEQ / 128), 256, attn_smem>>>();

    // 3) Output projection -> fp32 out
    gemm_hmma_kernel<1><<<dim3(HIDDEN / 128, MROWS / 128), 256, gemm_smem>>>(
        out_b, out, HIDDEN);
}